// round 2
// baseline (speedup 1.0000x reference)
#include <cuda_runtime.h>
#include <math.h>

// Problem shape (fixed)
#define B_ 2
#define S_ 2048
#define E_ 1024
#define H_ 16
#define D_ 64
#define M_ROWS (B_ * S_)   // 4096
#define N_QKV (3 * E_)     // 3072

// Scratch (allocation-free rule: __device__ globals)
__device__ float g_q[B_ * H_ * S_ * D_];   // [b,h,s,d]
__device__ float g_k[B_ * H_ * S_ * D_];
__device__ float g_v[B_ * H_ * S_ * D_];
__device__ float g_ao[B_ * S_ * E_];       // [b,s,e] attention output

// ---------------------------------------------------------------------------
// Kernel 1: QKV projection.  C[4096,3072] = X[4096,1024] @ Wqkv[1024,3072] + b
// scattered into g_q/g_k/g_v with layout [b,h,s,d].
// Classic SGEMM: BM=BN=128, BK=16, 256 threads, 8x8 per thread.
// ---------------------------------------------------------------------------
__global__ __launch_bounds__(256) void qkv_gemm_kernel(
    const float* __restrict__ X, const float* __restrict__ W,
    const float* __restrict__ bias)
{
    const int K = E_;
    __shared__ float As[16][128];
    __shared__ float Bs[16][128];

    int tid = threadIdx.x;
    int row0 = blockIdx.y * 128;
    int col0 = blockIdx.x * 128;
    int tx = tid & 15, ty = tid >> 4;
    int tm0 = ty * 8, tn0 = tx * 8;

    float acc[8][8] = {};
    float regM[8], regN[8];

    for (int k0 = 0; k0 < K; k0 += 16) {
        // A tile 128x16, transpose into As[k][m]  (512 float4, 256 threads)
        #pragma unroll
        for (int ld = 0; ld < 2; ld++) {
            int idx = tid + ld * 256;
            int r = idx >> 2;
            int kq = (idx & 3) * 4;
            float4 a = *(const float4*)(X + (size_t)(row0 + r) * K + k0 + kq);
            As[kq + 0][r] = a.x; As[kq + 1][r] = a.y;
            As[kq + 2][r] = a.z; As[kq + 3][r] = a.w;
        }
        // B tile 16x128, direct (512 float4)
        #pragma unroll
        for (int ld = 0; ld < 2; ld++) {
            int idx = tid + ld * 256;
            int kr = idx >> 5;
            int nq = (idx & 31) * 4;
            *(float4*)&Bs[kr][nq] =
                *(const float4*)(W + (size_t)(k0 + kr) * N_QKV + col0 + nq);
        }
        __syncthreads();
        #pragma unroll
        for (int kk = 0; kk < 16; kk++) {
            #pragma unroll
            for (int i = 0; i < 8; i += 4)
                *(float4*)&regM[i] = *(float4*)&As[kk][tm0 + i];
            #pragma unroll
            for (int i = 0; i < 8; i += 4)
                *(float4*)&regN[i] = *(float4*)&Bs[kk][tn0 + i];
            #pragma unroll
            for (int i = 0; i < 8; i++)
                #pragma unroll
                for (int j = 0; j < 8; j++)
                    acc[i][j] += regM[i] * regN[j];
        }
        __syncthreads();
    }

    // Epilogue: add bias, scatter to q/k/v [b,h,s,d]
    #pragma unroll
    for (int i = 0; i < 8; i++) {
        int r = row0 + tm0 + i;
        int b = r >> 11;          // r / S_
        int s = r & (S_ - 1);
        #pragma unroll
        for (int j = 0; j < 8; j += 4) {
            int c = col0 + tn0 + j;
            int t = c >> 10;       // 0=q 1=k 2=v
            int rem = c & 1023;
            int h = rem >> 6;
            int d = rem & 63;
            float* dst = (t == 0) ? g_q : (t == 1) ? g_k : g_v;
            size_t o = ((size_t)((b * H_ + h) * S_ + s)) * D_ + d;
            float4 v;
            v.x = acc[i][j + 0] + bias[c + 0];
            v.y = acc[i][j + 1] + bias[c + 1];
            v.z = acc[i][j + 2] + bias[c + 2];
            v.w = acc[i][j + 3] + bias[c + 3];
            *(float4*)(dst + o) = v;
        }
    }
}

// ---------------------------------------------------------------------------
// Kernel 2: flash attention (fp32, online softmax).
// grid = (S/128, B*H); 128 threads; one thread owns one query row.
// q[64] and o[64] live in registers; K/V tiles of KT=32 rows staged in SMEM.
// ---------------------------------------------------------------------------
#define KT 32

__global__ __launch_bounds__(128) void attn_kernel(const int* __restrict__ mask)
{
    int bh = blockIdx.y;
    int b = bh >> 4;           // / H_
    int qrow = blockIdx.x * 128 + threadIdx.x;
    int h = bh & 15;

    const float* Qp = g_q + ((size_t)bh * S_ + qrow) * D_;
    const float* Kbase = g_k + (size_t)bh * S_ * D_;
    const float* Vbase = g_v + (size_t)bh * S_ * D_;

    float q[64];
    #pragma unroll
    for (int i = 0; i < 64; i += 4) {
        float4 t = *(const float4*)(Qp + i);
        q[i + 0] = t.x * 0.125f;   // fold 1/sqrt(D)
        q[i + 1] = t.y * 0.125f;
        q[i + 2] = t.z * 0.125f;
        q[i + 3] = t.w * 0.125f;
    }

    float o[64];
    #pragma unroll
    for (int i = 0; i < 64; i++) o[i] = 0.f;
    float m = -INFINITY, l = 0.f;

    __shared__ float Ks[KT][64];
    __shared__ float Vs[KT][64];
    __shared__ float msk[KT];

    for (int kt = 0; kt < S_; kt += KT) {
        // load KT x 64 of K and V: KT*16 float4 each, 128 threads strided
        #pragma unroll
        for (int i = threadIdx.x; i < KT * 16; i += 128) {
            int rr = i >> 4, cc = (i & 15) * 4;
            *(float4*)&Ks[rr][cc] = *(const float4*)(Kbase + (size_t)(kt + rr) * D_ + cc);
            *(float4*)&Vs[rr][cc] = *(const float4*)(Vbase + (size_t)(kt + rr) * D_ + cc);
        }
        if (threadIdx.x < KT)
            msk[threadIdx.x] =
                (mask[b * S_ + kt + threadIdx.x] == 0) ? -INFINITY : 0.f;
        __syncthreads();

        float s[KT];
        #pragma unroll
        for (int j = 0; j < KT; j++) {
            float a = 0.f;
            #pragma unroll
            for (int dd = 0; dd < 64; dd += 4) {
                float4 kk = *(const float4*)&Ks[j][dd];
                a += q[dd + 0] * kk.x + q[dd + 1] * kk.y
                   + q[dd + 2] * kk.z + q[dd + 3] * kk.w;
            }
            s[j] = a + msk[j];
        }

        float mt = m;
        #pragma unroll
        for (int j = 0; j < KT; j++) mt = fmaxf(mt, s[j]);
        float scale = __expf(m - mt);
        l *= scale;
        #pragma unroll
        for (int dd = 0; dd < 64; dd++) o[dd] *= scale;

        #pragma unroll
        for (int j = 0; j < KT; j++) {
            float p = __expf(s[j] - mt);
            l += p;
            #pragma unroll
            for (int dd = 0; dd < 64; dd += 4) {
                float4 vv = *(const float4*)&Vs[j][dd];
                o[dd + 0] += p * vv.x;
                o[dd + 1] += p * vv.y;
                o[dd + 2] += p * vv.z;
                o[dd + 3] += p * vv.w;
            }
        }
        m = mt;
        __syncthreads();
    }

    float inv = 1.f / l;
    float* dst = g_ao + ((size_t)(b * S_ + qrow)) * E_ + h * D_;
    #pragma unroll
    for (int dd = 0; dd < 64; dd += 4) {
        float4 v;
        v.x = o[dd + 0] * inv; v.y = o[dd + 1] * inv;
        v.z = o[dd + 2] * inv; v.w = o[dd + 3] * inv;
        *(float4*)(dst + dd) = v;
    }
}

// ---------------------------------------------------------------------------
// Kernel 3: output projection.  out[4096,1024] = AO @ Wout + bout
// ---------------------------------------------------------------------------
__global__ __launch_bounds__(256) void out_gemm_kernel(
    const float* __restrict__ W, const float* __restrict__ bias,
    float* __restrict__ out)
{
    const int K = E_, N = E_;
    __shared__ float As[16][128];
    __shared__ float Bs[16][128];

    int tid = threadIdx.x;
    int row0 = blockIdx.y * 128;
    int col0 = blockIdx.x * 128;
    int tx = tid & 15, ty = tid >> 4;
    int tm0 = ty * 8, tn0 = tx * 8;

    float acc[8][8] = {};
    float regM[8], regN[8];

    for (int k0 = 0; k0 < K; k0 += 16) {
        #pragma unroll
        for (int ld = 0; ld < 2; ld++) {
            int idx = tid + ld * 256;
            int r = idx >> 2;
            int kq = (idx & 3) * 4;
            float4 a = *(const float4*)(g_ao + (size_t)(row0 + r) * K + k0 + kq);
            As[kq + 0][r] = a.x; As[kq + 1][r] = a.y;
            As[kq + 2][r] = a.z; As[kq + 3][r] = a.w;
        }
        #pragma unroll
        for (int ld = 0; ld < 2; ld++) {
            int idx = tid + ld * 256;
            int kr = idx >> 5;
            int nq = (idx & 31) * 4;
            *(float4*)&Bs[kr][nq] =
                *(const float4*)(W + (size_t)(k0 + kr) * N + col0 + nq);
        }
        __syncthreads();
        #pragma unroll
        for (int kk = 0; kk < 16; kk++) {
            #pragma unroll
            for (int i = 0; i < 8; i += 4)
                *(float4*)&regM[i] = *(float4*)&As[kk][tm0 + i];
            #pragma unroll
            for (int i = 0; i < 8; i += 4)
                *(float4*)&regN[i] = *(float4*)&Bs[kk][tn0 + i];
            #pragma unroll
            for (int i = 0; i < 8; i++)
                #pragma unroll
                for (int j = 0; j < 8; j++)
                    acc[i][j] += regM[i] * regN[j];
        }
        __syncthreads();
    }

    #pragma unroll
    for (int i = 0; i < 8; i++) {
        int r = row0 + tm0 + i;
        #pragma unroll
        for (int j = 0; j < 8; j += 4) {
            int c = col0 + tn0 + j;
            float4 v;
            v.x = acc[i][j + 0] + bias[c + 0];
            v.y = acc[i][j + 1] + bias[c + 1];
            v.z = acc[i][j + 2] + bias[c + 2];
            v.w = acc[i][j + 3] + bias[c + 3];
            *(float4*)(out + (size_t)r * N + c) = v;
        }
    }
}

// ---------------------------------------------------------------------------
extern "C" void kernel_launch(void* const* d_in, const int* in_sizes, int n_in,
                              void* d_out, int out_size)
{
    const float* x    = (const float*)d_in[0];
    const int*   mask = (const int*)  d_in[1];
    const float* Wqkv = (const float*)d_in[2];
    const float* bqkv = (const float*)d_in[3];
    const float* Wout = (const float*)d_in[4];
    const float* bout = (const float*)d_in[5];
    float* out = (float*)d_out;
    (void)in_sizes; (void)n_in; (void)out_size;

    dim3 g1(N_QKV / 128, M_ROWS / 128);   // 24 x 32
    qkv_gemm_kernel<<<g1, 256>>>(x, Wqkv, bqkv);

    dim3 g2(S_ / 128, B_ * H_);           // 16 x 32
    attn_kernel<<<g2, 128>>>(mask);

    dim3 g3(E_ / 128, M_ROWS / 128);      // 8 x 32
    out_gemm_kernel<<<g3, 256>>>(Wout, bout, out);
}

// round 4
// speedup vs baseline: 1.2454x; 1.2454x over previous
#include <cuda_runtime.h>
#include <math.h>
#include <stdint.h>

// Problem shape (fixed)
#define B_ 2
#define S_ 2048
#define E_ 1024
#define H_ 16
#define D_ 64
#define M_ROWS (B_ * S_)   // 4096
#define N_QKV (3 * E_)     // 3072

// Scratch (__device__ globals per allocation rules)
__device__ float g_q[B_ * H_ * S_ * D_];   // [b,h,s,d]
__device__ float g_k[B_ * H_ * S_ * D_];
__device__ float g_v[B_ * H_ * S_ * D_];
__device__ float g_ao[B_ * S_ * E_];       // [b,s,e]
__device__ float g_wqkv_t[(size_t)N_QKV * E_];  // Wqkv^T [N][K], tf32-rounded
__device__ float g_wout_t[(size_t)E_ * E_];     // Wout^T [N][K], tf32-rounded

__device__ __forceinline__ uint32_t cvt_tf32(float f) {
    uint32_t u;
    asm("cvt.rn.tf32.f32 %0, %1;" : "=r"(u) : "f"(f));
    return u;
}

__device__ __forceinline__ void mma_tf32(float* c, const uint32_t* a,
                                         const uint32_t* b) {
    asm volatile(
        "mma.sync.aligned.m16n8k8.row.col.f32.tf32.tf32.f32 "
        "{%0,%1,%2,%3}, {%4,%5,%6,%7}, {%8,%9}, {%0,%1,%2,%3};"
        : "+f"(c[0]), "+f"(c[1]), "+f"(c[2]), "+f"(c[3])
        : "r"(a[0]), "r"(a[1]), "r"(a[2]), "r"(a[3]), "r"(b[0]), "r"(b[1]));
}

// ---------------------------------------------------------------------------
// Weight transpose + tf32 rounding:  Wt[n][k] = rn_tf32(W[k][n])
// ---------------------------------------------------------------------------
__device__ __forceinline__ void transpose_body(const float* __restrict__ W,
                                               float* __restrict__ Wt,
                                               int K, int N) {
    __shared__ float tile[32][33];
    int n0 = blockIdx.x * 32, k0 = blockIdx.y * 32;
    int tx = threadIdx.x, ty = threadIdx.y;
    for (int i = ty; i < 32; i += 8)
        tile[i][tx] = W[(size_t)(k0 + i) * N + n0 + tx];
    __syncthreads();
    for (int i = ty; i < 32; i += 8)
        Wt[(size_t)(n0 + i) * K + k0 + tx] =
            __uint_as_float(cvt_tf32(tile[tx][i]));
}

__global__ void transpose_qkv_kernel(const float* __restrict__ W) {
    transpose_body(W, g_wqkv_t, E_, N_QKV);
}
__global__ void transpose_out_kernel(const float* __restrict__ W) {
    transpose_body(W, g_wout_t, E_, E_);
}

// ---------------------------------------------------------------------------
// tf32 mma.sync GEMM core.  C[4096, N] = A[4096,1024] @ Bt[N,1024]^T
// Tile 128x128, BK=32, 256 threads (8 warps -> 2x4 grid of 64x32 warp tiles).
// SMEM tiles [128 rows][36 cols] fp32: (4r+k)%32 banks -> conflict-free for
// the m16n8k8 fragment pattern (g=lane>>2, t4=lane&3).
// ---------------------------------------------------------------------------
#define BK 32
#define TSTRIDE 36
#define TILE_WORDS (128 * TSTRIDE)
#define GEMM_DYN_SMEM (2 * 2 * TILE_WORDS * 4)   // 73728 B

struct GemmFrag {
    float acc[4][4][4];   // [mfrag][nfrag][reg]
};

// Global->register staging: 4 float4 per thread per tile.
__device__ __forceinline__ void ldg_tile(const float* __restrict__ G,
                                         int rowbase, int kb, int tid,
                                         float4* r) {
    #pragma unroll
    for (int i = 0; i < 4; i++) {
        int idx = tid + i * 256;
        int row = idx >> 3, c4 = idx & 7;
        r[i] = *(const float4*)(G + (size_t)(rowbase + row) * E_ + kb * BK + c4 * 4);
    }
}

// Register->SMEM with tf32 RN rounding.
__device__ __forceinline__ void sts_tile(float* Sm, int tid, const float4* r) {
    #pragma unroll
    for (int i = 0; i < 4; i++) {
        int idx = tid + i * 256;
        int row = idx >> 3, c4 = idx & 7;
        uint32_t* p = (uint32_t*)(Sm + row * TSTRIDE + c4 * 4);
        p[0] = cvt_tf32(r[i].x);
        p[1] = cvt_tf32(r[i].y);
        p[2] = cvt_tf32(r[i].z);
        p[3] = cvt_tf32(r[i].w);
    }
}

__device__ __forceinline__ void gemm_compute(const float* As, const float* Bs,
                                             int warpM, int warpN, int lane,
                                             GemmFrag& F) {
    int g = lane >> 2, t4 = lane & 3;
    #pragma unroll
    for (int c = 0; c < 4; c++) {        // k-chunk of 8
        int k0 = c * 8;
        uint32_t a[4][4], b[4][2];
        #pragma unroll
        for (int mf = 0; mf < 4; mf++) {
            const float* ap = As + (warpM * 64 + mf * 16 + g) * TSTRIDE + k0 + t4;
            a[mf][0] = __float_as_uint(ap[0]);
            a[mf][1] = __float_as_uint(ap[8 * TSTRIDE]);
            a[mf][2] = __float_as_uint(ap[4]);
            a[mf][3] = __float_as_uint(ap[8 * TSTRIDE + 4]);
        }
        #pragma unroll
        for (int nf = 0; nf < 4; nf++) {
            const float* bp = Bs + (warpN * 32 + nf * 8 + g) * TSTRIDE + k0 + t4;
            b[nf][0] = __float_as_uint(bp[0]);
            b[nf][1] = __float_as_uint(bp[4]);
        }
        #pragma unroll
        for (int mf = 0; mf < 4; mf++)
            #pragma unroll
            for (int nf = 0; nf < 4; nf++)
                mma_tf32(F.acc[mf][nf], a[mf], b[nf]);
    }
}

// Full mainloop: leaves accumulators in F.
__device__ __forceinline__ void gemm_mainloop(const float* __restrict__ A,
                                              const float* __restrict__ Bt,
                                              int row0, int col0,
                                              float* dynsm, int tid,
                                              int warpM, int warpN, int lane,
                                              GemmFrag& F) {
    float* As[2] = { dynsm,                  dynsm + 2 * TILE_WORDS };
    float* Bs[2] = { dynsm + TILE_WORDS,     dynsm + 3 * TILE_WORDS };

    float4 ra[4], rb[4];
    ldg_tile(A,  row0, 0, tid, ra);
    ldg_tile(Bt, col0, 0, tid, rb);
    sts_tile(As[0], tid, ra);
    sts_tile(Bs[0], tid, rb);
    __syncthreads();

    const int NBK = E_ / BK;   // 32
    for (int kb = 0; kb < NBK; kb++) {
        int cur = kb & 1;
        if (kb + 1 < NBK) {
            ldg_tile(A,  row0, kb + 1, tid, ra);
            ldg_tile(Bt, col0, kb + 1, tid, rb);
        }
        gemm_compute(As[cur], Bs[cur], warpM, warpN, lane, F);
        if (kb + 1 < NBK) {
            sts_tile(As[cur ^ 1], tid, ra);
            sts_tile(Bs[cur ^ 1], tid, rb);
        }
        __syncthreads();
    }
}

// --- QKV GEMM: epilogue scatters into g_q/g_k/g_v [b,h,s,d] ---
__global__ __launch_bounds__(256) void qkv_mma_kernel(
    const float* __restrict__ X, const float* __restrict__ bias)
{
    extern __shared__ float dynsm[];
    int tid = threadIdx.x, wid = tid >> 5, lane = tid & 31;
    int warpM = wid & 1, warpN = wid >> 1;
    int row0 = blockIdx.y * 128, col0 = blockIdx.x * 128;

    GemmFrag F;
    #pragma unroll
    for (int i = 0; i < 4; i++)
        #pragma unroll
        for (int j = 0; j < 4; j++)
            #pragma unroll
            for (int k = 0; k < 4; k++) F.acc[i][j][k] = 0.f;

    gemm_mainloop(X, g_wqkv_t, row0, col0, dynsm, tid, warpM, warpN, lane, F);

    int g = lane >> 2, t4 = lane & 3;
    int t = col0 >> 10;                        // whole block in one of q/k/v
    float* dst = (t == 0) ? g_q : (t == 1) ? g_k : g_v;

    #pragma unroll
    for (int mf = 0; mf < 4; mf++) {
        #pragma unroll
        for (int nf = 0; nf < 4; nf++) {
            int col = col0 + warpN * 32 + nf * 8 + 2 * t4;
            int h = (col & 1023) >> 6;
            int d = col & 63;
            float bx = bias[col], by = bias[col + 1];
            #pragma unroll
            for (int rr = 0; rr < 2; rr++) {
                int row = row0 + warpM * 64 + mf * 16 + g + rr * 8;
                int bb = row >> 11, s = row & (S_ - 1);
                float2 v;
                v.x = F.acc[mf][nf][rr * 2 + 0] + bx;
                v.y = F.acc[mf][nf][rr * 2 + 1] + by;
                *(float2*)(dst + ((size_t)((bb * H_ + h) * S_ + s)) * D_ + d) = v;
            }
        }
    }
}

// --- Output GEMM: plain epilogue to d_out ---
__global__ __launch_bounds__(256) void out_mma_kernel(
    const float* __restrict__ bias, float* __restrict__ out)
{
    extern __shared__ float dynsm[];
    int tid = threadIdx.x, wid = tid >> 5, lane = tid & 31;
    int warpM = wid & 1, warpN = wid >> 1;
    int row0 = blockIdx.y * 128, col0 = blockIdx.x * 128;

    GemmFrag F;
    #pragma unroll
    for (int i = 0; i < 4; i++)
        #pragma unroll
        for (int j = 0; j < 4; j++)
            #pragma unroll
            for (int k = 0; k < 4; k++) F.acc[i][j][k] = 0.f;

    gemm_mainloop(g_ao, g_wout_t, row0, col0, dynsm, tid, warpM, warpN, lane, F);

    int g = lane >> 2, t4 = lane & 3;
    #pragma unroll
    for (int mf = 0; mf < 4; mf++) {
        #pragma unroll
        for (int nf = 0; nf < 4; nf++) {
            int col = col0 + warpN * 32 + nf * 8 + 2 * t4;
            float bx = bias[col], by = bias[col + 1];
            #pragma unroll
            for (int rr = 0; rr < 2; rr++) {
                int row = row0 + warpM * 64 + mf * 16 + g + rr * 8;
                float2 v;
                v.x = F.acc[mf][nf][rr * 2 + 0] + bx;
                v.y = F.acc[mf][nf][rr * 2 + 1] + by;
                *(float2*)(out + (size_t)row * E_ + col) = v;
            }
        }
    }
}

// ---------------------------------------------------------------------------
// Flash attention (fp32, online softmax) — unchanged from R2 passing kernel.
// ---------------------------------------------------------------------------
#define KT 32

__global__ __launch_bounds__(128) void attn_kernel(const int* __restrict__ mask)
{
    int bh = blockIdx.y;
    int b = bh >> 4;
    int qrow = blockIdx.x * 128 + threadIdx.x;
    int h = bh & 15;

    const float* Qp = g_q + ((size_t)bh * S_ + qrow) * D_;
    const float* Kbase = g_k + (size_t)bh * S_ * D_;
    const float* Vbase = g_v + (size_t)bh * S_ * D_;

    float q[64];
    #pragma unroll
    for (int i = 0; i < 64; i += 4) {
        float4 t = *(const float4*)(Qp + i);
        q[i + 0] = t.x * 0.125f;
        q[i + 1] = t.y * 0.125f;
        q[i + 2] = t.z * 0.125f;
        q[i + 3] = t.w * 0.125f;
    }

    float o[64];
    #pragma unroll
    for (int i = 0; i < 64; i++) o[i] = 0.f;
    float m = -INFINITY, l = 0.f;

    __shared__ float Ks[KT][64];
    __shared__ float Vs[KT][64];
    __shared__ float msk[KT];

    for (int kt = 0; kt < S_; kt += KT) {
        #pragma unroll
        for (int i = threadIdx.x; i < KT * 16; i += 128) {
            int rr = i >> 4, cc = (i & 15) * 4;
            *(float4*)&Ks[rr][cc] = *(const float4*)(Kbase + (size_t)(kt + rr) * D_ + cc);
            *(float4*)&Vs[rr][cc] = *(const float4*)(Vbase + (size_t)(kt + rr) * D_ + cc);
        }
        if (threadIdx.x < KT)
            msk[threadIdx.x] =
                (mask[b * S_ + kt + threadIdx.x] == 0) ? -INFINITY : 0.f;
        __syncthreads();

        float s[KT];
        #pragma unroll
        for (int j = 0; j < KT; j++) {
            float a = 0.f;
            #pragma unroll
            for (int dd = 0; dd < 64; dd += 4) {
                float4 kk = *(const float4*)&Ks[j][dd];
                a += q[dd + 0] * kk.x + q[dd + 1] * kk.y
                   + q[dd + 2] * kk.z + q[dd + 3] * kk.w;
            }
            s[j] = a + msk[j];
        }

        float mt = m;
        #pragma unroll
        for (int j = 0; j < KT; j++) mt = fmaxf(mt, s[j]);
        float scale = __expf(m - mt);
        l *= scale;
        #pragma unroll
        for (int dd = 0; dd < 64; dd++) o[dd] *= scale;

        #pragma unroll
        for (int j = 0; j < KT; j++) {
            float p = __expf(s[j] - mt);
            l += p;
            #pragma unroll
            for (int dd = 0; dd < 64; dd += 4) {
                float4 vv = *(const float4*)&Vs[j][dd];
                o[dd + 0] += p * vv.x;
                o[dd + 1] += p * vv.y;
                o[dd + 2] += p * vv.z;
                o[dd + 3] += p * vv.w;
            }
        }
        m = mt;
        __syncthreads();
    }

    float inv = 1.f / l;
    float* dst = g_ao + ((size_t)(b * S_ + qrow)) * E_ + h * D_;
    #pragma unroll
    for (int dd = 0; dd < 64; dd += 4) {
        float4 v;
        v.x = o[dd + 0] * inv; v.y = o[dd + 1] * inv;
        v.z = o[dd + 2] * inv; v.w = o[dd + 3] * inv;
        *(float4*)(dst + dd) = v;
    }
}

// ---------------------------------------------------------------------------
extern "C" void kernel_launch(void* const* d_in, const int* in_sizes, int n_in,
                              void* d_out, int out_size)
{
    const float* x    = (const float*)d_in[0];
    const int*   mask = (const int*)  d_in[1];
    const float* Wqkv = (const float*)d_in[2];
    const float* bqkv = (const float*)d_in[3];
    const float* Wout = (const float*)d_in[4];
    const float* bout = (const float*)d_in[5];
    float* out = (float*)d_out;
    (void)in_sizes; (void)n_in; (void)out_size;

    static bool attr_done = false;
    if (!attr_done) {
        cudaFuncSetAttribute(qkv_mma_kernel,
                             cudaFuncAttributeMaxDynamicSharedMemorySize, GEMM_DYN_SMEM);
        cudaFuncSetAttribute(out_mma_kernel,
                             cudaFuncAttributeMaxDynamicSharedMemorySize, GEMM_DYN_SMEM);
        attr_done = true;
    }

    transpose_qkv_kernel<<<dim3(N_QKV / 32, E_ / 32), dim3(32, 8)>>>(Wqkv);
    transpose_out_kernel<<<dim3(E_ / 32, E_ / 32), dim3(32, 8)>>>(Wout);

    dim3 g1(N_QKV / 128, M_ROWS / 128);   // 24 x 32
    qkv_mma_kernel<<<g1, 256, GEMM_DYN_SMEM>>>(x, bqkv);

    dim3 g2(S_ / 128, B_ * H_);           // 16 x 32
    attn_kernel<<<g2, 128>>>(mask);

    dim3 g3(E_ / 128, M_ROWS / 128);      // 8 x 32
    out_mma_kernel<<<g3, 256, GEMM_DYN_SMEM>>>(bout, out);
}

// round 5
// speedup vs baseline: 2.6450x; 2.1238x over previous
#include <cuda_runtime.h>
#include <math.h>
#include <stdint.h>

// Problem shape (fixed)
#define B_ 2
#define S_ 2048
#define E_ 1024
#define H_ 16
#define D_ 64
#define M_ROWS (B_ * S_)   // 4096
#define N_QKV (3 * E_)     // 3072

// Scratch (__device__ globals per allocation rules)
__device__ float g_q[B_ * H_ * S_ * D_];   // [b,h,s,d]
__device__ float g_k[B_ * H_ * S_ * D_];
__device__ float g_v[B_ * H_ * S_ * D_];
__device__ float g_ao[B_ * S_ * E_];       // [b,s,e]
__device__ float g_wqkv_t[(size_t)N_QKV * E_];  // Wqkv^T [N][K], tf32-rounded
__device__ float g_wout_t[(size_t)E_ * E_];     // Wout^T [N][K], tf32-rounded

__device__ __forceinline__ uint32_t cvt_tf32(float f) {
    uint32_t u;
    asm("cvt.rn.tf32.f32 %0, %1;" : "=r"(u) : "f"(f));
    return u;
}

__device__ __forceinline__ void mma_tf32(float* c, const uint32_t* a,
                                         const uint32_t* b) {
    asm volatile(
        "mma.sync.aligned.m16n8k8.row.col.f32.tf32.tf32.f32 "
        "{%0,%1,%2,%3}, {%4,%5,%6,%7}, {%8,%9}, {%0,%1,%2,%3};"
        : "+f"(c[0]), "+f"(c[1]), "+f"(c[2]), "+f"(c[3])
        : "r"(a[0]), "r"(a[1]), "r"(a[2]), "r"(a[3]), "r"(b[0]), "r"(b[1]));
}

// ---------------------------------------------------------------------------
// Weight transpose + tf32 rounding:  Wt[n][k] = rn_tf32(W[k][n])
// ---------------------------------------------------------------------------
__device__ __forceinline__ void transpose_body(const float* __restrict__ W,
                                               float* __restrict__ Wt,
                                               int K, int N) {
    __shared__ float tile[32][33];
    int n0 = blockIdx.x * 32, k0 = blockIdx.y * 32;
    int tx = threadIdx.x, ty = threadIdx.y;
    for (int i = ty; i < 32; i += 8)
        tile[i][tx] = W[(size_t)(k0 + i) * N + n0 + tx];
    __syncthreads();
    for (int i = ty; i < 32; i += 8)
        Wt[(size_t)(n0 + i) * K + k0 + tx] =
            __uint_as_float(cvt_tf32(tile[tx][i]));
}

__global__ void transpose_qkv_kernel(const float* __restrict__ W) {
    transpose_body(W, g_wqkv_t, E_, N_QKV);
}
__global__ void transpose_out_kernel(const float* __restrict__ W) {
    transpose_body(W, g_wout_t, E_, E_);
}

// ---------------------------------------------------------------------------
// tf32 mma.sync projection GEMM core (unchanged from R4, passing).
// ---------------------------------------------------------------------------
#define BK 32
#define TSTRIDE 36
#define TILE_WORDS (128 * TSTRIDE)
#define GEMM_DYN_SMEM (2 * 2 * TILE_WORDS * 4)   // 73728 B

struct GemmFrag {
    float acc[4][4][4];   // [mfrag][nfrag][reg]
};

__device__ __forceinline__ void ldg_tile(const float* __restrict__ G,
                                         int rowbase, int kb, int tid,
                                         float4* r) {
    #pragma unroll
    for (int i = 0; i < 4; i++) {
        int idx = tid + i * 256;
        int row = idx >> 3, c4 = idx & 7;
        r[i] = *(const float4*)(G + (size_t)(rowbase + row) * E_ + kb * BK + c4 * 4);
    }
}

__device__ __forceinline__ void sts_tile(float* Sm, int tid, const float4* r) {
    #pragma unroll
    for (int i = 0; i < 4; i++) {
        int idx = tid + i * 256;
        int row = idx >> 3, c4 = idx & 7;
        uint32_t* p = (uint32_t*)(Sm + row * TSTRIDE + c4 * 4);
        p[0] = cvt_tf32(r[i].x);
        p[1] = cvt_tf32(r[i].y);
        p[2] = cvt_tf32(r[i].z);
        p[3] = cvt_tf32(r[i].w);
    }
}

__device__ __forceinline__ void gemm_compute(const float* As, const float* Bs,
                                             int warpM, int warpN, int lane,
                                             GemmFrag& F) {
    int g = lane >> 2, t4 = lane & 3;
    #pragma unroll
    for (int c = 0; c < 4; c++) {
        int k0 = c * 8;
        uint32_t a[4][4], b[4][2];
        #pragma unroll
        for (int mf = 0; mf < 4; mf++) {
            const float* ap = As + (warpM * 64 + mf * 16 + g) * TSTRIDE + k0 + t4;
            a[mf][0] = __float_as_uint(ap[0]);
            a[mf][1] = __float_as_uint(ap[8 * TSTRIDE]);
            a[mf][2] = __float_as_uint(ap[4]);
            a[mf][3] = __float_as_uint(ap[8 * TSTRIDE + 4]);
        }
        #pragma unroll
        for (int nf = 0; nf < 4; nf++) {
            const float* bp = Bs + (warpN * 32 + nf * 8 + g) * TSTRIDE + k0 + t4;
            b[nf][0] = __float_as_uint(bp[0]);
            b[nf][1] = __float_as_uint(bp[4]);
        }
        #pragma unroll
        for (int mf = 0; mf < 4; mf++)
            #pragma unroll
            for (int nf = 0; nf < 4; nf++)
                mma_tf32(F.acc[mf][nf], a[mf], b[nf]);
    }
}

__device__ __forceinline__ void gemm_mainloop(const float* __restrict__ A,
                                              const float* __restrict__ Bt,
                                              int row0, int col0,
                                              float* dynsm, int tid,
                                              int warpM, int warpN, int lane,
                                              GemmFrag& F) {
    float* As[2] = { dynsm,              dynsm + 2 * TILE_WORDS };
    float* Bs[2] = { dynsm + TILE_WORDS, dynsm + 3 * TILE_WORDS };

    float4 ra[4], rb[4];
    ldg_tile(A,  row0, 0, tid, ra);
    ldg_tile(Bt, col0, 0, tid, rb);
    sts_tile(As[0], tid, ra);
    sts_tile(Bs[0], tid, rb);
    __syncthreads();

    const int NBK = E_ / BK;
    for (int kb = 0; kb < NBK; kb++) {
        int cur = kb & 1;
        if (kb + 1 < NBK) {
            ldg_tile(A,  row0, kb + 1, tid, ra);
            ldg_tile(Bt, col0, kb + 1, tid, rb);
        }
        gemm_compute(As[cur], Bs[cur], warpM, warpN, lane, F);
        if (kb + 1 < NBK) {
            sts_tile(As[cur ^ 1], tid, ra);
            sts_tile(Bs[cur ^ 1], tid, rb);
        }
        __syncthreads();
    }
}

__global__ __launch_bounds__(256) void qkv_mma_kernel(
    const float* __restrict__ X, const float* __restrict__ bias)
{
    extern __shared__ float dynsm[];
    int tid = threadIdx.x, wid = tid >> 5, lane = tid & 31;
    int warpM = wid & 1, warpN = wid >> 1;
    int row0 = blockIdx.y * 128, col0 = blockIdx.x * 128;

    GemmFrag F;
    #pragma unroll
    for (int i = 0; i < 4; i++)
        #pragma unroll
        for (int j = 0; j < 4; j++)
            #pragma unroll
            for (int k = 0; k < 4; k++) F.acc[i][j][k] = 0.f;

    gemm_mainloop(X, g_wqkv_t, row0, col0, dynsm, tid, warpM, warpN, lane, F);

    int g = lane >> 2, t4 = lane & 3;
    int t = col0 >> 10;
    float* dst = (t == 0) ? g_q : (t == 1) ? g_k : g_v;

    #pragma unroll
    for (int mf = 0; mf < 4; mf++) {
        #pragma unroll
        for (int nf = 0; nf < 4; nf++) {
            int col = col0 + warpN * 32 + nf * 8 + 2 * t4;
            int h = (col & 1023) >> 6;
            int d = col & 63;
            float bx = bias[col], by = bias[col + 1];
            #pragma unroll
            for (int rr = 0; rr < 2; rr++) {
                int row = row0 + warpM * 64 + mf * 16 + g + rr * 8;
                int bb = row >> 11, s = row & (S_ - 1);
                float2 v;
                v.x = F.acc[mf][nf][rr * 2 + 0] + bx;
                v.y = F.acc[mf][nf][rr * 2 + 1] + by;
                *(float2*)(dst + ((size_t)((bb * H_ + h) * S_ + s)) * D_ + d) = v;
            }
        }
    }
}

__global__ __launch_bounds__(256) void out_mma_kernel(
    const float* __restrict__ bias, float* __restrict__ out)
{
    extern __shared__ float dynsm[];
    int tid = threadIdx.x, wid = tid >> 5, lane = tid & 31;
    int warpM = wid & 1, warpN = wid >> 1;
    int row0 = blockIdx.y * 128, col0 = blockIdx.x * 128;

    GemmFrag F;
    #pragma unroll
    for (int i = 0; i < 4; i++)
        #pragma unroll
        for (int j = 0; j < 4; j++)
            #pragma unroll
            for (int k = 0; k < 4; k++) F.acc[i][j][k] = 0.f;

    gemm_mainloop(g_ao, g_wout_t, row0, col0, dynsm, tid, warpM, warpN, lane, F);

    int g = lane >> 2, t4 = lane & 3;
    #pragma unroll
    for (int mf = 0; mf < 4; mf++) {
        #pragma unroll
        for (int nf = 0; nf < 4; nf++) {
            int col = col0 + warpN * 32 + nf * 8 + 2 * t4;
            float bx = bias[col], by = bias[col + 1];
            #pragma unroll
            for (int rr = 0; rr < 2; rr++) {
                int row = row0 + warpM * 64 + mf * 16 + g + rr * 8;
                float2 v;
                v.x = F.acc[mf][nf][rr * 2 + 0] + bx;
                v.y = F.acc[mf][nf][rr * 2 + 1] + by;
                *(float2*)(out + (size_t)row * E_ + col) = v;
            }
        }
    }
}

// ---------------------------------------------------------------------------
// Flash attention on tf32 mma.sync.
// Grid (S/128, B*H), 256 threads = 8 warps; warp w owns q-rows [16w,16w+16).
// K-tile = 64.  SMEM: Kt[64][72], Vt[64][72], P[128][76], msk[64].
// Strides 72/76 chosen conflict-free for the m16n8k8 fragment patterns.
// ---------------------------------------------------------------------------
#define AKT 64
#define KVSTR 72
#define PSTR 76
#define KT_OFF 0
#define VT_OFF (64 * KVSTR)                 // 4608
#define P_OFF  (VT_OFF + 64 * KVSTR)        // 9216
#define MSK_OFF (P_OFF + 128 * PSTR)        // 18944
#define ATTN_DYN_SMEM ((MSK_OFF + 64) * 4)  // 76032 B

__global__ __launch_bounds__(256) void attn_mma_kernel(const int* __restrict__ mask)
{
    extern __shared__ float sm[];
    float* Kt = sm + KT_OFF;
    float* Vt = sm + VT_OFF;
    float* P  = sm + P_OFF;
    float* mk = sm + MSK_OFF;

    int tid = threadIdx.x, w = tid >> 5, lane = tid & 31;
    int g = lane >> 2, t4 = lane & 3;
    int bh = blockIdx.y;
    int b = bh >> 4, h = bh & 15;
    int q0 = blockIdx.x * 128;
    int wrow = w * 16;                 // warp's q-row base within tile

    const float* Qb = g_q + (size_t)bh * S_ * D_;
    const float* Kb = g_k + (size_t)bh * S_ * D_;
    const float* Vb = g_v + (size_t)bh * S_ * D_;

    // Q fragments in registers (scale folded, tf32-rounded)
    uint32_t qa[8][4];
    {
        int r0 = q0 + wrow + g, r1 = r0 + 8;
        #pragma unroll
        for (int dc = 0; dc < 8; dc++) {
            int d0 = dc * 8 + t4;
            qa[dc][0] = cvt_tf32(Qb[(size_t)r0 * D_ + d0]     * 0.125f);
            qa[dc][1] = cvt_tf32(Qb[(size_t)r1 * D_ + d0]     * 0.125f);
            qa[dc][2] = cvt_tf32(Qb[(size_t)r0 * D_ + d0 + 4] * 0.125f);
            qa[dc][3] = cvt_tf32(Qb[(size_t)r1 * D_ + d0 + 4] * 0.125f);
        }
    }

    float ov[8][4];
    #pragma unroll
    for (int i = 0; i < 8; i++)
        #pragma unroll
        for (int j = 0; j < 4; j++) ov[i][j] = 0.f;
    float m0 = -1e30f, m1 = -1e30f, l0 = 0.f, l1 = 0.f;

    for (int kt = 0; kt < S_; kt += AKT) {
        __syncthreads();   // prior-tile PV done before overwriting Kt/Vt
        // Stage K/V tile (64x64 each): 4 float4 per thread per tensor.
        #pragma unroll
        for (int i = 0; i < 4; i++) {
            int idx = tid + i * 256;
            int row = idx >> 4, c4 = (idx & 15) * 4;
            float4 kv = *(const float4*)(Kb + (size_t)(kt + row) * D_ + c4);
            uint32_t* p = (uint32_t*)(Kt + row * KVSTR + c4);
            p[0] = cvt_tf32(kv.x); p[1] = cvt_tf32(kv.y);
            p[2] = cvt_tf32(kv.z); p[3] = cvt_tf32(kv.w);
            float4 vv = *(const float4*)(Vb + (size_t)(kt + row) * D_ + c4);
            uint32_t* pv = (uint32_t*)(Vt + row * KVSTR + c4);
            pv[0] = cvt_tf32(vv.x); pv[1] = cvt_tf32(vv.y);
            pv[2] = cvt_tf32(vv.z); pv[3] = cvt_tf32(vv.w);
        }
        if (tid < AKT)
            mk[tid] = (mask[b * S_ + kt + tid] == 0) ? -INFINITY : 0.f;
        __syncthreads();

        // QK^T: S-frags [16 x 64] per warp
        float s[8][4];
        #pragma unroll
        for (int i = 0; i < 8; i++)
            #pragma unroll
            for (int j = 0; j < 4; j++) s[i][j] = 0.f;
        #pragma unroll
        for (int dc = 0; dc < 8; dc++) {
            #pragma unroll
            for (int nf = 0; nf < 8; nf++) {
                const float* bp = Kt + (nf * 8 + g) * KVSTR + dc * 8 + t4;
                uint32_t bfr[2] = { __float_as_uint(bp[0]), __float_as_uint(bp[4]) };
                mma_tf32(s[nf], qa[dc], bfr);
            }
        }

        // mask + row max
        float mx0 = -INFINITY, mx1 = -INFINITY;
        #pragma unroll
        for (int nf = 0; nf < 8; nf++) {
            float a0 = mk[nf * 8 + 2 * t4], a1 = mk[nf * 8 + 2 * t4 + 1];
            s[nf][0] += a0; s[nf][1] += a1; s[nf][2] += a0; s[nf][3] += a1;
            mx0 = fmaxf(mx0, fmaxf(s[nf][0], s[nf][1]));
            mx1 = fmaxf(mx1, fmaxf(s[nf][2], s[nf][3]));
        }
        mx0 = fmaxf(mx0, __shfl_xor_sync(0xffffffffu, mx0, 1));
        mx0 = fmaxf(mx0, __shfl_xor_sync(0xffffffffu, mx0, 2));
        mx1 = fmaxf(mx1, __shfl_xor_sync(0xffffffffu, mx1, 1));
        mx1 = fmaxf(mx1, __shfl_xor_sync(0xffffffffu, mx1, 2));

        float mn0 = fmaxf(m0, mx0), mn1 = fmaxf(m1, mx1);  // >= -1e30, finite
        float sc0 = __expf(m0 - mn0), sc1 = __expf(m1 - mn1);
        l0 *= sc0; l1 *= sc1;
        #pragma unroll
        for (int nf = 0; nf < 8; nf++) {
            ov[nf][0] *= sc0; ov[nf][1] *= sc0;
            ov[nf][2] *= sc1; ov[nf][3] *= sc1;
        }

        // p = exp(s - m), accumulate l, store tf32 P
        float* prow0 = P + (wrow + g) * PSTR;
        float* prow1 = P + (wrow + g + 8) * PSTR;
        #pragma unroll
        for (int nf = 0; nf < 8; nf++) {
            float p0 = __expf(s[nf][0] - mn0);
            float p1 = __expf(s[nf][1] - mn0);
            float p2 = __expf(s[nf][2] - mn1);
            float p3 = __expf(s[nf][3] - mn1);
            l0 += p0 + p1; l1 += p2 + p3;
            uint32_t* d0 = (uint32_t*)(prow0 + nf * 8 + 2 * t4);
            uint32_t* d1 = (uint32_t*)(prow1 + nf * 8 + 2 * t4);
            d0[0] = cvt_tf32(p0); d0[1] = cvt_tf32(p1);
            d1[0] = cvt_tf32(p2); d1[1] = cvt_tf32(p3);
        }
        m0 = mn0; m1 = mn1;
        __syncwarp();   // P round-trip is warp-local

        // PV: out += P[16x64] @ V[64x64]
        #pragma unroll
        for (int kc = 0; kc < 8; kc++) {
            const float* ar0 = P + (wrow + g) * PSTR + kc * 8 + t4;
            const float* ar1 = P + (wrow + g + 8) * PSTR + kc * 8 + t4;
            uint32_t a[4] = { __float_as_uint(ar0[0]), __float_as_uint(ar1[0]),
                              __float_as_uint(ar0[4]), __float_as_uint(ar1[4]) };
            #pragma unroll
            for (int nf = 0; nf < 8; nf++) {
                const float* bp0 = Vt + (kc * 8 + t4) * KVSTR + nf * 8 + g;
                const float* bp1 = Vt + (kc * 8 + t4 + 4) * KVSTR + nf * 8 + g;
                uint32_t bfr[2] = { __float_as_uint(bp0[0]), __float_as_uint(bp1[0]) };
                mma_tf32(ov[nf], a, bfr);
            }
        }
    }

    // finalize: quad-reduce l, normalize, write g_ao [b, s, h*64+d]
    l0 += __shfl_xor_sync(0xffffffffu, l0, 1);
    l0 += __shfl_xor_sync(0xffffffffu, l0, 2);
    l1 += __shfl_xor_sync(0xffffffffu, l1, 1);
    l1 += __shfl_xor_sync(0xffffffffu, l1, 2);
    float inv0 = 1.f / l0, inv1 = 1.f / l1;

    int r0 = q0 + wrow + g, r1 = r0 + 8;
    float* o0 = g_ao + ((size_t)(b * S_ + r0)) * E_ + h * D_;
    float* o1 = g_ao + ((size_t)(b * S_ + r1)) * E_ + h * D_;
    #pragma unroll
    for (int nf = 0; nf < 8; nf++) {
        int d = nf * 8 + 2 * t4;
        float2 v0 = { ov[nf][0] * inv0, ov[nf][1] * inv0 };
        float2 v1 = { ov[nf][2] * inv1, ov[nf][3] * inv1 };
        *(float2*)(o0 + d) = v0;
        *(float2*)(o1 + d) = v1;
    }
}

// ---------------------------------------------------------------------------
extern "C" void kernel_launch(void* const* d_in, const int* in_sizes, int n_in,
                              void* d_out, int out_size)
{
    const float* x    = (const float*)d_in[0];
    const int*   mask = (const int*)  d_in[1];
    const float* Wqkv = (const float*)d_in[2];
    const float* bqkv = (const float*)d_in[3];
    const float* Wout = (const float*)d_in[4];
    const float* bout = (const float*)d_in[5];
    float* out = (float*)d_out;
    (void)in_sizes; (void)n_in; (void)out_size;

    static bool attr_done = false;
    if (!attr_done) {
        cudaFuncSetAttribute(qkv_mma_kernel,
                             cudaFuncAttributeMaxDynamicSharedMemorySize, GEMM_DYN_SMEM);
        cudaFuncSetAttribute(out_mma_kernel,
                             cudaFuncAttributeMaxDynamicSharedMemorySize, GEMM_DYN_SMEM);
        cudaFuncSetAttribute(attn_mma_kernel,
                             cudaFuncAttributeMaxDynamicSharedMemorySize, ATTN_DYN_SMEM);
        attr_done = true;
    }

    transpose_qkv_kernel<<<dim3(N_QKV / 32, E_ / 32), dim3(32, 8)>>>(Wqkv);
    transpose_out_kernel<<<dim3(E_ / 32, E_ / 32), dim3(32, 8)>>>(Wout);

    dim3 g1(N_QKV / 128, M_ROWS / 128);   // 24 x 32
    qkv_mma_kernel<<<g1, 256, GEMM_DYN_SMEM>>>(x, bqkv);

    dim3 g2(S_ / 128, B_ * H_);           // 16 x 32
    attn_mma_kernel<<<g2, 256, ATTN_DYN_SMEM>>>(mask);

    dim3 g3(E_ / 128, M_ROWS / 128);      // 8 x 32
    out_mma_kernel<<<g3, 256, GEMM_DYN_SMEM>>>(bout, out);
}